// round 6
// baseline (speedup 1.0000x reference)
#include <cuda_runtime.h>
#include <cuda_bf16.h>
#include <cstdint>

#define B_    4
#define SQ_   2048
#define SK_   2048
#define D_    1024
#define H_    16
#define HD_   64
#define SCALE_ 0.125f
#define M_TOT (B_ * SQ_)   // 8192

// ---------------------------------------------------------------------------
// Scratch (__device__ globals per allocation rules)
// ---------------------------------------------------------------------------
__device__ float g_Q  [(size_t)M_TOT * D_];
__device__ float g_KV [(size_t)M_TOT * 2 * D_];
__device__ float g_ctx[(size_t)M_TOT * D_];

__device__ __nv_bfloat16 g_qh[(size_t)M_TOT * D_], g_ql[(size_t)M_TOT * D_];
__device__ __nv_bfloat16 g_kh[(size_t)M_TOT * D_], g_kl[(size_t)M_TOT * D_];
__device__ __nv_bfloat16 g_ch[(size_t)M_TOT * D_], g_cl[(size_t)M_TOT * D_];

__device__ __nv_bfloat16 g_WqTh[D_ * D_],      g_WqTl[D_ * D_];
__device__ __nv_bfloat16 g_WkvTh[2 * D_ * D_], g_WkvTl[2 * D_ * D_];
__device__ __nv_bfloat16 g_WoTh[D_ * D_],      g_WoTl[D_ * D_];

// Per-head split arrays for attention: [b*H + h][seq][64]
__device__ __nv_bfloat16 g_Qh2[(size_t)M_TOT * D_], g_Ql2[(size_t)M_TOT * D_];
__device__ __nv_bfloat16 g_Kh2[(size_t)M_TOT * D_], g_Kl2[(size_t)M_TOT * D_];
__device__ __nv_bfloat16 g_Vh2[(size_t)M_TOT * D_], g_Vl2[(size_t)M_TOT * D_];

// ---------------------------------------------------------------------------
// Helpers
// ---------------------------------------------------------------------------
__device__ __forceinline__ uint32_t smem_u32(const void* p) {
    uint32_t a;
    asm("{ .reg .u64 t; cvta.to.shared.u64 t, %1; cvt.u32.u64 %0, t; }" : "=r"(a) : "l"(p));
    return a;
}

#define SW128(off) ((off) ^ (((off) >> 3) & 0x70))

#define CP16(dst, src) \
    asm volatile("cp.async.cg.shared.global [%0], [%1], 16;" \
                 :: "r"(dst), "l"(src) : "memory")
#define CP_COMMIT() asm volatile("cp.async.commit_group;" ::: "memory")
#define CP_WAIT1()  asm volatile("cp.async.wait_group 1;" ::: "memory")

#define LDSM_X4(r, addr) \
    asm volatile("ldmatrix.sync.aligned.m8n8.x4.shared.b16 {%0,%1,%2,%3}, [%4];" \
                 : "=r"((r)[0]), "=r"((r)[1]), "=r"((r)[2]), "=r"((r)[3]) : "r"(addr))
#define LDSM_X4_T(r, addr) \
    asm volatile("ldmatrix.sync.aligned.m8n8.x4.trans.shared.b16 {%0,%1,%2,%3}, [%4];" \
                 : "=r"((r)[0]), "=r"((r)[1]), "=r"((r)[2]), "=r"((r)[3]) : "r"(addr))

#define MMA16816(c, a, b) \
    asm volatile("mma.sync.aligned.m16n8k16.row.col.f32.bf16.bf16.f32 " \
                 "{%0,%1,%2,%3}, {%4,%5,%6,%7}, {%8,%9}, {%0,%1,%2,%3};" \
                 : "+f"((c)[0]), "+f"((c)[1]), "+f"((c)[2]), "+f"((c)[3]) \
                 : "r"((a)[0]), "r"((a)[1]), "r"((a)[2]), "r"((a)[3]), \
                   "r"((b)[0]), "r"((b)[1]))

__device__ __forceinline__ void split2(float x, float y, uint32_t& hi, uint32_t& lo) {
    __nv_bfloat162 h = __floats2bfloat162_rn(x, y);
    float hx = __bfloat162float(h.x), hy = __bfloat162float(h.y);
    __nv_bfloat162 l = __floats2bfloat162_rn(x - hx, y - hy);
    hi = reinterpret_cast<uint32_t&>(h);
    lo = reinterpret_cast<uint32_t&>(l);
}

// ---------------------------------------------------------------------------
// Prep kernels
// ---------------------------------------------------------------------------
__global__ void prep_act(const float* __restrict__ X,
                         __nv_bfloat16* __restrict__ Xh,
                         __nv_bfloat16* __restrict__ Xl, int n4) {
    int i = blockIdx.x * blockDim.x + threadIdx.x;
    int stride = gridDim.x * blockDim.x;
    for (; i < n4; i += stride) {
        float4 v = ((const float4*)X)[i];
        uint32_t h0, l0, h1, l1;
        split2(v.x, v.y, h0, l0);
        split2(v.z, v.w, h1, l1);
        ((uint32_t*)Xh)[i * 2 + 0] = h0;
        ((uint32_t*)Xh)[i * 2 + 1] = h1;
        ((uint32_t*)Xl)[i * 2 + 0] = l0;
        ((uint32_t*)Xl)[i * 2 + 1] = l1;
    }
}

__global__ void prep_wT(const float* __restrict__ W,
                        __nv_bfloat16* __restrict__ Th,
                        __nv_bfloat16* __restrict__ Tl, int Kd, int Nd) {
    __shared__ float t[32][33];
    int n  = blockIdx.x * 32 + threadIdx.x;
    int k0 = blockIdx.y * 32;
    for (int i = threadIdx.y; i < 32; i += 8)
        t[i][threadIdx.x] = W[(size_t)(k0 + i) * Nd + n];
    __syncthreads();
    int nn = blockIdx.x * 32;
    for (int i = threadIdx.y; i < 32; i += 8) {
        float v = t[threadIdx.x][i];
        __nv_bfloat16 h = __float2bfloat16_rn(v);
        Th[(size_t)(nn + i) * Kd + k0 + threadIdx.x] = h;
        Tl[(size_t)(nn + i) * Kd + k0 + threadIdx.x] =
            __float2bfloat16_rn(v - __bfloat162float(h));
    }
}

__global__ void prep_split_qkv(const float* __restrict__ Q, const float* __restrict__ KV,
                               __nv_bfloat16* __restrict__ Qh, __nv_bfloat16* __restrict__ Ql,
                               __nv_bfloat16* __restrict__ Kh, __nv_bfloat16* __restrict__ Kl,
                               __nv_bfloat16* __restrict__ Vh, __nv_bfloat16* __restrict__ Vl) {
    const int total = M_TOT * D_ / 2;   // 4M
    int idx = blockIdx.x * blockDim.x + threadIdx.x;
    int stride = gridDim.x * blockDim.x;
    for (; idx < total; idx += stride) {
        int d2 = idx & 31;
        int s  = (idx >> 5) & 2047;
        int bh = idx >> 16;
        int h = bh & 15, b = bh >> 4;
        size_t qsrc = ((size_t)(b * SQ_ + s)) * D_ + h * 64 + d2 * 2;
        size_t ksrc = ((size_t)(b * SK_ + s)) * (2 * D_) + h * 64 + d2 * 2;
        float2 qv = *(const float2*)(Q + qsrc);
        float2 kv = *(const float2*)(KV + ksrc);
        float2 vv = *(const float2*)(KV + ksrc + D_);
        uint32_t hi, lo;
        split2(qv.x, qv.y, hi, lo);
        ((uint32_t*)Qh)[idx] = hi; ((uint32_t*)Ql)[idx] = lo;
        split2(kv.x, kv.y, hi, lo);
        ((uint32_t*)Kh)[idx] = hi; ((uint32_t*)Kl)[idx] = lo;
        split2(vv.x, vv.y, hi, lo);
        ((uint32_t*)Vh)[idx] = hi; ((uint32_t*)Vl)[idx] = lo;
    }
}

// ---------------------------------------------------------------------------
// Tensor-core GEMM v2: CTA tile 256x128 (high arithmetic intensity),
// warp tile 64x64 (4x2 warps), BK=32, 3-stage cp.async, 1 CTA/SM.
// Smem/stage: A 256x128B (32KB) + B 128x128B (16KB) = 48KB; row = hi|lo.
// ---------------------------------------------------------------------------
#define BK2       32
#define STAGES2   3
#define A_BYTES2  32768u
#define STAGE2    49152u
#define GEMM_SMEM (1024 + STAGES2 * STAGE2)

__global__ __launch_bounds__(256, 1) void gemm_mma(
    const __nv_bfloat16* __restrict__ Ah, const __nv_bfloat16* __restrict__ Al,
    const __nv_bfloat16* __restrict__ Bh, const __nv_bfloat16* __restrict__ Bl,
    const float* __restrict__ bias, float* __restrict__ C, int N, int K)
{
    extern __shared__ char smraw[];
    const uint32_t raw32  = smem_u32(smraw);
    const uint32_t heap32 = (raw32 + 1023) & ~1023u;

    const int tid  = threadIdx.x;
    const int lane = tid & 31, wid = tid >> 5;
    const int wm0  = (wid & 3) * 64;      // 4 warps over M=256
    const int wn0  = (wid >> 2) * 64;     // 2 warps over N=128
    const int m0   = blockIdx.y * 256;
    const int n0   = blockIdx.x * 128;

    // ---- loaders ----
    // A: thread t -> row t (256 rows), 4 hi + 4 lo segs (full 128B row)
    const __nv_bfloat16* gah = Ah + (size_t)(m0 + tid) * K;
    const __nv_bfloat16* gal = Al + (size_t)(m0 + tid) * K;
    uint32_t aswz[8];
    #pragma unroll
    for (int s = 0; s < 4; s++) {
        aswz[s]     = SW128((uint32_t)(tid * 128 + s * 16));
        aswz[4 + s] = SW128((uint32_t)(tid * 128 + 64 + s * 16));
    }
    // B: 2 threads per row; thread t -> row t&127, half (t>>7): 2 hi + 2 lo segs
    const int brow = tid & 127, bhalf = tid >> 7;
    const __nv_bfloat16* gbh = Bh + (size_t)(n0 + brow) * K + bhalf * 16;
    const __nv_bfloat16* gbl = Bl + (size_t)(n0 + brow) * K + bhalf * 16;
    uint32_t bswz[4];
    #pragma unroll
    for (int s = 0; s < 2; s++) {
        bswz[s]     = SW128((uint32_t)(brow * 128 + bhalf * 32 + s * 16));
        bswz[2 + s] = SW128((uint32_t)(brow * 128 + 64 + bhalf * 32 + s * 16));
    }

    float acc[4][8][4];
    #pragma unroll
    for (int mt = 0; mt < 4; mt++)
        #pragma unroll
        for (int nt = 0; nt < 8; nt++)
            #pragma unroll
            for (int r = 0; r < 4; r++) acc[mt][nt][r] = 0.f;

    const uint32_t aRowOff = (uint32_t)((wm0 + (lane & 15)) * 128 + ((lane >> 4) << 4));
    const uint32_t bRowOff = (uint32_t)((wn0 + (lane & 15)) * 128 + ((lane >> 4) << 4));

    const int steps = K / BK2;

    // prologue: stages 0,1
    #pragma unroll
    for (int s = 0; s < 2; s++) {
        const uint32_t stg = heap32 + (uint32_t)s * STAGE2;
        const int k0 = s * BK2;
        #pragma unroll
        for (int seg = 0; seg < 4; seg++) {
            CP16(stg + aswz[seg],     gah + k0 + seg * 8);
            CP16(stg + aswz[4 + seg], gal + k0 + seg * 8);
        }
        #pragma unroll
        for (int seg = 0; seg < 2; seg++) {
            CP16(stg + A_BYTES2 + bswz[seg],     gbh + k0 + seg * 8);
            CP16(stg + A_BYTES2 + bswz[2 + seg], gbl + k0 + seg * 8);
        }
        CP_COMMIT();
    }

    for (int i = 0; i < steps; i++) {
        CP_WAIT1();
        __syncthreads();

        if (i + 2 < steps) {
            const uint32_t stg = heap32 + (uint32_t)((i + 2) % STAGES2) * STAGE2;
            const int k0 = (i + 2) * BK2;
            #pragma unroll
            for (int seg = 0; seg < 4; seg++) {
                CP16(stg + aswz[seg],     gah + k0 + seg * 8);
                CP16(stg + aswz[4 + seg], gal + k0 + seg * 8);
            }
            #pragma unroll
            for (int seg = 0; seg < 2; seg++) {
                CP16(stg + A_BYTES2 + bswz[seg],     gbh + k0 + seg * 8);
                CP16(stg + A_BYTES2 + bswz[2 + seg], gbl + k0 + seg * 8);
            }
        }
        CP_COMMIT();

        const uint32_t aB = heap32 + (uint32_t)(i % STAGES2) * STAGE2;
        const uint32_t bB = aB + A_BYTES2;

        #pragma unroll
        for (int kh = 0; kh < 2; kh++) {
            uint32_t afh[4][4], afl[4][4];
            #pragma unroll
            for (int mt = 0; mt < 4; mt++) {
                uint32_t off = aRowOff + (uint32_t)(mt * 16 * 128 + kh * 32);
                LDSM_X4(afh[mt], aB + SW128(off));
                LDSM_X4(afl[mt], aB + SW128(off + 64));
            }
            #pragma unroll
            for (int p = 0; p < 4; p++) {
                uint32_t b4h[4], b4l[4];
                uint32_t off = bRowOff + (uint32_t)(p * 16 * 128 + kh * 32);
                LDSM_X4(b4h, bB + SW128(off));
                LDSM_X4(b4l, bB + SW128(off + 64));
                uint32_t bh0[2] = {b4h[0], b4h[2]}, bh1[2] = {b4h[1], b4h[3]};
                uint32_t bl0[2] = {b4l[0], b4l[2]}, bl1[2] = {b4l[1], b4l[3]};
                #pragma unroll
                for (int mt = 0; mt < 4; mt++) {
                    MMA16816(acc[mt][2 * p],     afh[mt], bh0);
                    MMA16816(acc[mt][2 * p],     afh[mt], bl0);
                    MMA16816(acc[mt][2 * p],     afl[mt], bh0);
                    MMA16816(acc[mt][2 * p + 1], afh[mt], bh1);
                    MMA16816(acc[mt][2 * p + 1], afh[mt], bl1);
                    MMA16816(acc[mt][2 * p + 1], afl[mt], bh1);
                }
            }
        }
    }

    // epilogue: direct stores + bias
    const int erow = lane >> 2, ecol = (lane & 3) * 2;
    #pragma unroll
    for (int nt = 0; nt < 8; nt++) {
        int col = n0 + wn0 + nt * 8 + ecol;
        float2 bv = *(const float2*)&bias[col];
        #pragma unroll
        for (int mt = 0; mt < 4; mt++) {
            int row = m0 + wm0 + mt * 16 + erow;
            float2 v0, v1;
            v0.x = acc[mt][nt][0] + bv.x;  v0.y = acc[mt][nt][1] + bv.y;
            v1.x = acc[mt][nt][2] + bv.x;  v1.y = acc[mt][nt][3] + bv.y;
            *(float2*)&C[(size_t)row * N + col]       = v0;
            *(float2*)&C[(size_t)(row + 8) * N + col] = v1;
        }
    }
}

// ---------------------------------------------------------------------------
// Tensor-core flash attention (unchanged, validated in R5)
// ---------------------------------------------------------------------------
#define ATTN_SMEM (98304 + 1024)

__global__ __launch_bounds__(256, 2) void attn_tc(
    const __nv_bfloat16* __restrict__ Qh2, const __nv_bfloat16* __restrict__ Ql2,
    const __nv_bfloat16* __restrict__ Kh2, const __nv_bfloat16* __restrict__ Kl2,
    const __nv_bfloat16* __restrict__ Vh2, const __nv_bfloat16* __restrict__ Vl2,
    float* __restrict__ ctx)
{
    extern __shared__ char smraw[];
    const uint32_t raw32  = smem_u32(smraw);
    const uint32_t heap32 = (raw32 + 1023) & ~1023u;

    const int tid  = threadIdx.x;
    const int lane = tid & 31, wid = tid >> 5;
    const int q0 = blockIdx.x * 128;
    const int h  = blockIdx.y, b = blockIdx.z;
    const int bh = b * H_ + h;
    const size_t headQ = (size_t)bh * SQ_ * 64;
    const size_t headK = (size_t)bh * SK_ * 64;

    const uint32_t QH = heap32, QL = heap32 + 16384;
    #define STG(s) (heap32 + 32768u + (uint32_t)(s) * 32768u)

    {
        const int arr = tid >> 7, r = tid & 127;
        const __nv_bfloat16* src = (arr ? Ql2 : Qh2) + headQ + (size_t)(q0 + r) * 64;
        const uint32_t dst = heap32 + (uint32_t)arr * 16384u;
        #pragma unroll
        for (int seg = 0; seg < 8; seg++)
            CP16(dst + SW128((uint32_t)(r * 128 + seg * 16)), src + seg * 8);
    }
    const int larr = tid >> 6, lrow = tid & 63;
    const __nv_bfloat16* lsrc0 =
        (larr == 0 ? Kh2 : larr == 1 ? Kl2 : larr == 2 ? Vh2 : Vl2) + headK + (size_t)lrow * 64;
    uint32_t lsw[8];
    #pragma unroll
    for (int seg = 0; seg < 8; seg++)
        lsw[seg] = (uint32_t)larr * 8192u + SW128((uint32_t)(lrow * 128 + seg * 16));

    #pragma unroll
    for (int seg = 0; seg < 8; seg++)
        CP16(STG(0) + lsw[seg], lsrc0 + seg * 8);
    CP_COMMIT();

    float oacc[8][4];
    #pragma unroll
    for (int nt = 0; nt < 8; nt++)
        #pragma unroll
        for (int r = 0; r < 4; r++) oacc[nt][r] = 0.f;
    float mrow[2] = {-1e30f, -1e30f}, lrowsum[2] = {0.f, 0.f};

    const float c2 = SCALE_ * 1.44269504088896340736f;
    const int wm = wid * 16;
    const uint32_t aOff = (uint32_t)((wm + (lane & 15)) * 128 + ((lane >> 4) << 4));
    const uint32_t kOff = (uint32_t)((lane & 15) * 128 + ((lane >> 4) << 4));
    const uint32_t vOff = (uint32_t)((lane & 15) * 128 + ((lane >> 4) << 4));

    const int iters = SK_ / 64;
    for (int i = 0; i < iters; i++) {
        __syncthreads();
        if (i + 1 < iters) {
            const __nv_bfloat16* src = lsrc0 + (size_t)(i + 1) * 64 * 64;
            const uint32_t stg = STG((i + 1) & 1);
            #pragma unroll
            for (int seg = 0; seg < 8; seg++)
                CP16(stg + lsw[seg], src + seg * 8);
        }
        CP_COMMIT();
        CP_WAIT1();
        __syncthreads();

        const uint32_t KH = STG(i & 1), KL = KH + 8192, VH = KH + 16384, VL = KH + 24576;

        float sacc[8][4];
        #pragma unroll
        for (int nt = 0; nt < 8; nt++)
            #pragma unroll
            for (int r = 0; r < 4; r++) sacc[nt][r] = 0.f;

        #pragma unroll
        for (int kc = 0; kc < 4; kc++) {
            uint32_t afh[4], afl[4];
            LDSM_X4(afh, QH + SW128(aOff + kc * 32));
            LDSM_X4(afl, QL + SW128(aOff + kc * 32));
            #pragma unroll
            for (int ntp = 0; ntp < 4; ntp++) {
                uint32_t b4h[4], b4l[4];
                uint32_t off = kOff + (uint32_t)(ntp * 2048 + kc * 32);
                LDSM_X4(b4h, KH + SW128(off));
                LDSM_X4(b4l, KL + SW128(off));
                uint32_t bh0[2] = {b4h[0], b4h[2]}, bh1[2] = {b4h[1], b4h[3]};
                uint32_t bl0[2] = {b4l[0], b4l[2]}, bl1[2] = {b4l[1], b4l[3]};
                MMA16816(sacc[2 * ntp],     afh, bh0);
                MMA16816(sacc[2 * ntp],     afh, bl0);
                MMA16816(sacc[2 * ntp],     afl, bh0);
                MMA16816(sacc[2 * ntp + 1], afh, bh1);
                MMA16816(sacc[2 * ntp + 1], afh, bl1);
                MMA16816(sacc[2 * ntp + 1], afl, bh1);
            }
        }

        float fac[2];
        #pragma unroll
        for (int j = 0; j < 2; j++) {
            float tmax = -1e30f;
            #pragma unroll
            for (int nt = 0; nt < 8; nt++)
                tmax = fmaxf(tmax, fmaxf(sacc[nt][2 * j], sacc[nt][2 * j + 1]));
            tmax = fmaxf(tmax, __shfl_xor_sync(0xffffffffu, tmax, 1));
            tmax = fmaxf(tmax, __shfl_xor_sync(0xffffffffu, tmax, 2));
            float mn = fmaxf(mrow[j], tmax);
            fac[j] = exp2f((mrow[j] - mn) * c2);
            mrow[j] = mn;
            float tsum = 0.f;
            #pragma unroll
            for (int nt = 0; nt < 8; nt++) {
                float p0 = exp2f((sacc[nt][2 * j]     - mn) * c2);
                float p1 = exp2f((sacc[nt][2 * j + 1] - mn) * c2);
                sacc[nt][2 * j] = p0; sacc[nt][2 * j + 1] = p1;
                tsum += p0 + p1;
            }
            tsum += __shfl_xor_sync(0xffffffffu, tsum, 1);
            tsum += __shfl_xor_sync(0xffffffffu, tsum, 2);
            lrowsum[j] = lrowsum[j] * fac[j] + tsum;
            #pragma unroll
            for (int nt = 0; nt < 8; nt++) {
                oacc[nt][2 * j]     *= fac[j];
                oacc[nt][2 * j + 1] *= fac[j];
            }
        }

        #pragma unroll
        for (int kc = 0; kc < 4; kc++) {
            uint32_t ah[4], al[4];
            split2(sacc[2 * kc][0],     sacc[2 * kc][1],     ah[0], al[0]);
            split2(sacc[2 * kc][2],     sacc[2 * kc][3],     ah[1], al[1]);
            split2(sacc[2 * kc + 1][0], sacc[2 * kc + 1][1], ah[2], al[2]);
            split2(sacc[2 * kc + 1][2], sacc[2 * kc + 1][3], ah[3], al[3]);
            #pragma unroll
            for (int ntp = 0; ntp < 4; ntp++) {
                uint32_t v4h[4], v4l[4];
                uint32_t off = vOff + (uint32_t)(kc * 2048 + ntp * 32);
                LDSM_X4_T(v4h, VH + SW128(off));
                LDSM_X4_T(v4l, VL + SW128(off));
                uint32_t bh0[2] = {v4h[0], v4h[1]}, bh1[2] = {v4h[2], v4h[3]};
                uint32_t bl0[2] = {v4l[0], v4l[1]}, bl1[2] = {v4l[2], v4l[3]};
                MMA16816(oacc[2 * ntp],     ah, bh0);
                MMA16816(oacc[2 * ntp],     ah, bl0);
                MMA16816(oacc[2 * ntp],     al, bh0);
                MMA16816(oacc[2 * ntp + 1], ah, bh1);
                MMA16816(oacc[2 * ntp + 1], ah, bl1);
                MMA16816(oacc[2 * ntp + 1], al, bh1);
            }
        }
    }

    const float inv0 = 1.f / lrowsum[0], inv1 = 1.f / lrowsum[1];
    const int r0 = q0 + wm + (lane >> 2);
    const int col0 = h * 64 + (lane & 3) * 2;
    #pragma unroll
    for (int nt = 0; nt < 8; nt++) {
        int col = col0 + nt * 8;
        float2 v0, v1;
        v0.x = oacc[nt][0] * inv0;  v0.y = oacc[nt][1] * inv0;
        v1.x = oacc[nt][2] * inv1;  v1.y = oacc[nt][3] * inv1;
        *(float2*)&ctx[((size_t)(b * SQ_ + r0))     * D_ + col] = v0;
        *(float2*)&ctx[((size_t)(b * SQ_ + r0 + 8)) * D_ + col] = v1;
    }
}

// ---------------------------------------------------------------------------
extern "C" void kernel_launch(void* const* d_in, const int* in_sizes, int n_in,
                              void* d_out, int out_size)
{
    const float* query     = (const float*)d_in[0];
    const float* key_value = (const float*)d_in[1];
    const float* Wq        = (const float*)d_in[2];
    const float* bq        = (const float*)d_in[3];
    const float* Wkv       = (const float*)d_in[4];
    const float* bkv       = (const float*)d_in[5];
    const float* Wo        = (const float*)d_in[6];
    const float* bo        = (const float*)d_in[7];
    float* out = (float*)d_out;

    float *Qb, *KVb, *Ctx;
    __nv_bfloat16 *qh, *ql, *kh, *kl, *ch, *cl;
    __nv_bfloat16 *WqTh, *WqTl, *WkvTh, *WkvTl, *WoTh, *WoTl;
    __nv_bfloat16 *Qh2, *Ql2, *Kh2, *Kl2, *Vh2, *Vl2;
    cudaGetSymbolAddress((void**)&Qb,   g_Q);
    cudaGetSymbolAddress((void**)&KVb,  g_KV);
    cudaGetSymbolAddress((void**)&Ctx,  g_ctx);
    cudaGetSymbolAddress((void**)&qh,   g_qh);   cudaGetSymbolAddress((void**)&ql, g_ql);
    cudaGetSymbolAddress((void**)&kh,   g_kh);   cudaGetSymbolAddress((void**)&kl, g_kl);
    cudaGetSymbolAddress((void**)&ch,   g_ch);   cudaGetSymbolAddress((void**)&cl, g_cl);
    cudaGetSymbolAddress((void**)&WqTh, g_WqTh); cudaGetSymbolAddress((void**)&WqTl, g_WqTl);
    cudaGetSymbolAddress((void**)&WkvTh,g_WkvTh);cudaGetSymbolAddress((void**)&WkvTl,g_WkvTl);
    cudaGetSymbolAddress((void**)&WoTh, g_WoTh); cudaGetSymbolAddress((void**)&WoTl, g_WoTl);
    cudaGetSymbolAddress((void**)&Qh2,  g_Qh2);  cudaGetSymbolAddress((void**)&Ql2, g_Ql2);
    cudaGetSymbolAddress((void**)&Kh2,  g_Kh2);  cudaGetSymbolAddress((void**)&Kl2, g_Kl2);
    cudaGetSymbolAddress((void**)&Vh2,  g_Vh2);  cudaGetSymbolAddress((void**)&Vl2, g_Vl2);

    cudaFuncSetAttribute(gemm_mma, cudaFuncAttributeMaxDynamicSharedMemorySize, GEMM_SMEM);
    cudaFuncSetAttribute(attn_tc,  cudaFuncAttributeMaxDynamicSharedMemorySize, ATTN_SMEM);

    // Weight transpose + split
    prep_wT<<<dim3(D_ / 32,     D_ / 32), dim3(32, 8)>>>(Wq,  WqTh,  WqTl,  D_, D_);
    prep_wT<<<dim3(2 * D_ / 32, D_ / 32), dim3(32, 8)>>>(Wkv, WkvTh, WkvTl, D_, 2 * D_);
    prep_wT<<<dim3(D_ / 32,     D_ / 32), dim3(32, 8)>>>(Wo,  WoTh,  WoTl,  D_, D_);

    // Activation splits
    prep_act<<<2048, 256>>>(query,     qh, ql, M_TOT * D_ / 4);
    prep_act<<<2048, 256>>>(key_value, kh, kl, M_TOT * D_ / 4);

    // Projections (tensor cores, 256x128 tiles)
    gemm_mma<<<dim3(D_ / 128,     M_TOT / 256), 256, GEMM_SMEM>>>(
        qh, ql, WqTh, WqTl, bq, Qb, D_, D_);
    gemm_mma<<<dim3(2 * D_ / 128, M_TOT / 256), 256, GEMM_SMEM>>>(
        kh, kl, WkvTh, WkvTl, bkv, KVb, 2 * D_, D_);

    // Split + per-head rearrange for attention
    prep_split_qkv<<<2048, 256>>>(Qb, KVb, Qh2, Ql2, Kh2, Kl2, Vh2, Vl2);

    // Attention (tensor cores)
    attn_tc<<<dim3(SQ_ / 128, H_, B_), 256, ATTN_SMEM>>>(
        Qh2, Ql2, Kh2, Kl2, Vh2, Vl2, Ctx);

    // O projection
    prep_act<<<2048, 256>>>(Ctx, ch, cl, M_TOT * D_ / 4);
    gemm_mma<<<dim3(D_ / 128, M_TOT / 256), 256, GEMM_SMEM>>>(
        ch, cl, WoTh, WoTl, bo, out, D_, D_);
}

// round 7
// speedup vs baseline: 1.0225x; 1.0225x over previous
#include <cuda_runtime.h>
#include <cuda_bf16.h>
#include <cstdint>

#define B_    4
#define SQ_   2048
#define SK_   2048
#define D_    1024
#define H_    16
#define HD_   64
#define SCALE_ 0.125f
#define M_TOT (B_ * SQ_)   // 8192

// ---------------------------------------------------------------------------
// Scratch (__device__ globals per allocation rules)
// ---------------------------------------------------------------------------
__device__ __nv_bfloat16 g_qh[(size_t)M_TOT * D_], g_ql[(size_t)M_TOT * D_];
__device__ __nv_bfloat16 g_kh[(size_t)M_TOT * D_], g_kl[(size_t)M_TOT * D_];
__device__ __nv_bfloat16 g_ch[(size_t)M_TOT * D_], g_cl[(size_t)M_TOT * D_];

__device__ __nv_bfloat16 g_WqTh[D_ * D_],      g_WqTl[D_ * D_];
__device__ __nv_bfloat16 g_WkvTh[2 * D_ * D_], g_WkvTl[2 * D_ * D_];
__device__ __nv_bfloat16 g_WoTh[D_ * D_],      g_WoTl[D_ * D_];

// Per-head split arrays for attention: [b*H + h][seq][64]
__device__ __nv_bfloat16 g_Qh2[(size_t)M_TOT * D_], g_Ql2[(size_t)M_TOT * D_];
__device__ __nv_bfloat16 g_Kh2[(size_t)M_TOT * D_], g_Kl2[(size_t)M_TOT * D_];
__device__ __nv_bfloat16 g_Vh2[(size_t)M_TOT * D_], g_Vl2[(size_t)M_TOT * D_];

// ---------------------------------------------------------------------------
// Helpers
// ---------------------------------------------------------------------------
__device__ __forceinline__ uint32_t smem_u32(const void* p) {
    uint32_t a;
    asm("{ .reg .u64 t; cvta.to.shared.u64 t, %1; cvt.u32.u64 %0, t; }" : "=r"(a) : "l"(p));
    return a;
}

#define SW128(off) ((off) ^ (((off) >> 3) & 0x70))

#define CP16(dst, src) \
    asm volatile("cp.async.cg.shared.global [%0], [%1], 16;" \
                 :: "r"(dst), "l"(src) : "memory")
#define CP_COMMIT() asm volatile("cp.async.commit_group;" ::: "memory")
#define CP_WAIT1()  asm volatile("cp.async.wait_group 1;" ::: "memory")

#define LDSM_X4(r, addr) \
    asm volatile("ldmatrix.sync.aligned.m8n8.x4.shared.b16 {%0,%1,%2,%3}, [%4];" \
                 : "=r"((r)[0]), "=r"((r)[1]), "=r"((r)[2]), "=r"((r)[3]) : "r"(addr))
#define LDSM_X4_T(r, addr) \
    asm volatile("ldmatrix.sync.aligned.m8n8.x4.trans.shared.b16 {%0,%1,%2,%3}, [%4];" \
                 : "=r"((r)[0]), "=r"((r)[1]), "=r"((r)[2]), "=r"((r)[3]) : "r"(addr))
#define LDSM_X2(r, addr) \
    asm volatile("ldmatrix.sync.aligned.m8n8.x2.shared.b16 {%0,%1}, [%2];" \
                 : "=r"((r)[0]), "=r"((r)[1]) : "r"(addr))

#define MMA16816(c, a, b) \
    asm volatile("mma.sync.aligned.m16n8k16.row.col.f32.bf16.bf16.f32 " \
                 "{%0,%1,%2,%3}, {%4,%5,%6,%7}, {%8,%9}, {%0,%1,%2,%3};" \
                 : "+f"((c)[0]), "+f"((c)[1]), "+f"((c)[2]), "+f"((c)[3]) \
                 : "r"((a)[0]), "r"((a)[1]), "r"((a)[2]), "r"((a)[3]), \
                   "r"((b)[0]), "r"((b)[1]))

__device__ __forceinline__ void split2(float x, float y, uint32_t& hi, uint32_t& lo) {
    __nv_bfloat162 h = __floats2bfloat162_rn(x, y);
    float hx = __bfloat162float(h.x), hy = __bfloat162float(h.y);
    __nv_bfloat162 l = __floats2bfloat162_rn(x - hx, y - hy);
    hi = reinterpret_cast<uint32_t&>(h);
    lo = reinterpret_cast<uint32_t&>(l);
}

// ---------------------------------------------------------------------------
// Prep kernels
// ---------------------------------------------------------------------------
__global__ void prep_act(const float* __restrict__ X,
                         __nv_bfloat16* __restrict__ Xh,
                         __nv_bfloat16* __restrict__ Xl, int n4) {
    int i = blockIdx.x * blockDim.x + threadIdx.x;
    int stride = gridDim.x * blockDim.x;
    for (; i < n4; i += stride) {
        float4 v = ((const float4*)X)[i];
        uint32_t h0, l0, h1, l1;
        split2(v.x, v.y, h0, l0);
        split2(v.z, v.w, h1, l1);
        ((uint32_t*)Xh)[i * 2 + 0] = h0;
        ((uint32_t*)Xh)[i * 2 + 1] = h1;
        ((uint32_t*)Xl)[i * 2 + 0] = l0;
        ((uint32_t*)Xl)[i * 2 + 1] = l1;
    }
}

__global__ void prep_wT(const float* __restrict__ W,
                        __nv_bfloat16* __restrict__ Th,
                        __nv_bfloat16* __restrict__ Tl, int Kd, int Nd) {
    __shared__ float t[32][33];
    int n  = blockIdx.x * 32 + threadIdx.x;
    int k0 = blockIdx.y * 32;
    for (int i = threadIdx.y; i < 32; i += 8)
        t[i][threadIdx.x] = W[(size_t)(k0 + i) * Nd + n];
    __syncthreads();
    int nn = blockIdx.x * 32;
    for (int i = threadIdx.y; i < 32; i += 8) {
        float v = t[threadIdx.x][i];
        __nv_bfloat16 h = __float2bfloat16_rn(v);
        Th[(size_t)(nn + i) * Kd + k0 + threadIdx.x] = h;
        Tl[(size_t)(nn + i) * Kd + k0 + threadIdx.x] =
            __float2bfloat16_rn(v - __bfloat162float(h));
    }
}

// ---------------------------------------------------------------------------
// Tensor-core GEMM (R5 config: 128x128 tile, BK=32, 3-stage, 2 CTA/SM).
// mode 0: fp32 out C[M,N] (+bias)
// mode 1: Q-proj -> split bf16 per-head layout (Oh0/Ol0), N=1024
// mode 2: KV-proj -> K half into Oh0/Ol0, V half into Oh1/Ol1, N=2048
// ---------------------------------------------------------------------------
#define BK      32
#define STAGES  3
#define STAGE_BYTES 32768
#define GEMM_SMEM (1024 + STAGES * STAGE_BYTES)

__global__ __launch_bounds__(256, 2) void gemm_mma(
    const __nv_bfloat16* __restrict__ Ah, const __nv_bfloat16* __restrict__ Al,
    const __nv_bfloat16* __restrict__ Bh, const __nv_bfloat16* __restrict__ Bl,
    const float* __restrict__ bias, float* __restrict__ C,
    __nv_bfloat16* __restrict__ Oh0, __nv_bfloat16* __restrict__ Ol0,
    __nv_bfloat16* __restrict__ Oh1, __nv_bfloat16* __restrict__ Ol1,
    int mode, int N, int K)
{
    extern __shared__ char smraw[];
    const uint32_t raw32  = smem_u32(smraw);
    const uint32_t heap32 = (raw32 + 1023) & ~1023u;

    const int tid  = threadIdx.x;
    const int lane = tid & 31, wid = tid >> 5;
    const int wm0  = (wid & 3) * 32;
    const int wn0  = (wid >> 2) * 64;
    const int m0   = blockIdx.y * 128;
    const int n0   = blockIdx.x * 128;

    const bool isA = tid < 128;
    const int  lrow = isA ? tid : tid - 128;
    const __nv_bfloat16* gh = isA ? Ah + (size_t)(m0 + lrow) * K
                                  : Bh + (size_t)(n0 + lrow) * K;
    const __nv_bfloat16* gl = isA ? Al + (size_t)(m0 + lrow) * K
                                  : Bl + (size_t)(n0 + lrow) * K;
    const uint32_t dstBase = heap32 + (isA ? 0u : 16384u);
    uint32_t dsw[8];
    #pragma unroll
    for (int seg = 0; seg < 4; seg++) {
        dsw[seg]     = SW128((uint32_t)(lrow * 128 + seg * 16));
        dsw[4 + seg] = SW128((uint32_t)(lrow * 128 + 64 + seg * 16));
    }

    float acc[2][8][4];
    #pragma unroll
    for (int mt = 0; mt < 2; mt++)
        #pragma unroll
        for (int nt = 0; nt < 8; nt++)
            #pragma unroll
            for (int r = 0; r < 4; r++) acc[mt][nt][r] = 0.f;

    const uint32_t aRowOff = (uint32_t)((wm0 + (lane & 15)) * 128 + ((lane >> 4) << 4));
    const uint32_t bRowOff = (uint32_t)((wn0 + (lane & 7)) * 128 + (((lane >> 3) & 1) << 4));

    const int steps = K / BK;

    #pragma unroll
    for (int s = 0; s < 2; s++) {
        #pragma unroll
        for (int seg = 0; seg < 4; seg++) {
            CP16(dstBase + s * STAGE_BYTES + dsw[seg],     gh + s * BK + seg * 8);
            CP16(dstBase + s * STAGE_BYTES + dsw[4 + seg], gl + s * BK + seg * 8);
        }
        CP_COMMIT();
    }

    for (int i = 0; i < steps; i++) {
        CP_WAIT1();
        __syncthreads();

        if (i + 2 < steps) {
            const int s = (i + 2) % STAGES;
            const int k0 = (i + 2) * BK;
            #pragma unroll
            for (int seg = 0; seg < 4; seg++) {
                CP16(dstBase + s * STAGE_BYTES + dsw[seg],     gh + k0 + seg * 8);
                CP16(dstBase + s * STAGE_BYTES + dsw[4 + seg], gl + k0 + seg * 8);
            }
        }
        CP_COMMIT();

        const uint32_t aB = heap32 + (i % STAGES) * STAGE_BYTES;
        const uint32_t bB = aB + 16384;

        #pragma unroll
        for (int kh = 0; kh < 2; kh++) {
            uint32_t afh[2][4], afl[2][4];
            #pragma unroll
            for (int mt = 0; mt < 2; mt++) {
                uint32_t off = aRowOff + (uint32_t)(mt * 16 * 128 + kh * 32);
                LDSM_X4(afh[mt], aB + SW128(off));
                LDSM_X4(afl[mt], aB + SW128(off + 64));
            }
            #pragma unroll
            for (int nt = 0; nt < 8; nt++) {
                uint32_t off = bRowOff + (uint32_t)(nt * 8 * 128 + kh * 32);
                uint32_t bfh[2], bfl[2];
                LDSM_X2(bfh, bB + SW128(off));
                LDSM_X2(bfl, bB + SW128(off + 64));
                #pragma unroll
                for (int mt = 0; mt < 2; mt++) {
                    MMA16816(acc[mt][nt], afh[mt], bfh);
                    MMA16816(acc[mt][nt], afh[mt], bfl);
                    MMA16816(acc[mt][nt], afl[mt], bfh);
                }
            }
        }
    }

    // ---- epilogue ----
    const int erow = lane >> 2, ecol = (lane & 3) * 2;
    if (mode == 0) {
        #pragma unroll
        for (int nt = 0; nt < 8; nt++) {
            int col = n0 + wn0 + nt * 8 + ecol;
            float2 bv = *(const float2*)&bias[col];
            #pragma unroll
            for (int mt = 0; mt < 2; mt++) {
                int row = m0 + wm0 + mt * 16 + erow;
                float2 v0, v1;
                v0.x = acc[mt][nt][0] + bv.x;  v0.y = acc[mt][nt][1] + bv.y;
                v1.x = acc[mt][nt][2] + bv.x;  v1.y = acc[mt][nt][3] + bv.y;
                *(float2*)&C[(size_t)row * N + col]       = v0;
                *(float2*)&C[(size_t)(row + 8) * N + col] = v1;
            }
        }
    } else {
        // split bf16 per-head layout: dst = ((b*16+h)*2048 + s)*64 + d
        #pragma unroll
        for (int nt = 0; nt < 8; nt++) {
            int n = n0 + wn0 + nt * 8 + ecol;
            float2 bv = *(const float2*)&bias[n];
            __nv_bfloat16 *oh, *ol;
            int h, d = n & 63;
            if (mode == 1 || n < 1024) { h = (n & 1023) >> 6; oh = Oh0; ol = Ol0; }
            else                        { h = (n - 1024) >> 6; oh = Oh1; ol = Ol1; }
            #pragma unroll
            for (int mt = 0; mt < 2; mt++) {
                int row = m0 + wm0 + mt * 16 + erow;
                int b = row >> 11, s = row & 2047;
                size_t didx = (((size_t)(b * 16 + h)) * 2048 + s) * 64 + d;
                uint32_t hi, lo;
                split2(acc[mt][nt][0] + bv.x, acc[mt][nt][1] + bv.y, hi, lo);
                *(uint32_t*)&oh[didx] = hi;
                *(uint32_t*)&ol[didx] = lo;
                split2(acc[mt][nt][2] + bv.x, acc[mt][nt][3] + bv.y, hi, lo);
                *(uint32_t*)&oh[didx + 8 * 64] = hi;
                *(uint32_t*)&ol[didx + 8 * 64] = lo;
            }
        }
    }
}

// ---------------------------------------------------------------------------
// Tensor-core flash attention (R5-validated core; epilogue writes split bf16)
// ---------------------------------------------------------------------------
#define ATTN_SMEM (98304 + 1024)

__global__ __launch_bounds__(256, 2) void attn_tc(
    const __nv_bfloat16* __restrict__ Qh2, const __nv_bfloat16* __restrict__ Ql2,
    const __nv_bfloat16* __restrict__ Kh2, const __nv_bfloat16* __restrict__ Kl2,
    const __nv_bfloat16* __restrict__ Vh2, const __nv_bfloat16* __restrict__ Vl2,
    __nv_bfloat16* __restrict__ ch, __nv_bfloat16* __restrict__ cl)
{
    extern __shared__ char smraw[];
    const uint32_t raw32  = smem_u32(smraw);
    const uint32_t heap32 = (raw32 + 1023) & ~1023u;

    const int tid  = threadIdx.x;
    const int lane = tid & 31, wid = tid >> 5;
    const int q0 = blockIdx.x * 128;
    const int h  = blockIdx.y, b = blockIdx.z;
    const int bh = b * H_ + h;
    const size_t headQ = (size_t)bh * SQ_ * 64;
    const size_t headK = (size_t)bh * SK_ * 64;

    const uint32_t QH = heap32, QL = heap32 + 16384;
    #define STG(s) (heap32 + 32768u + (uint32_t)(s) * 32768u)

    {
        const int arr = tid >> 7, r = tid & 127;
        const __nv_bfloat16* src = (arr ? Ql2 : Qh2) + headQ + (size_t)(q0 + r) * 64;
        const uint32_t dst = heap32 + (uint32_t)arr * 16384u;
        #pragma unroll
        for (int seg = 0; seg < 8; seg++)
            CP16(dst + SW128((uint32_t)(r * 128 + seg * 16)), src + seg * 8);
    }
    const int larr = tid >> 6, lrow = tid & 63;
    const __nv_bfloat16* lsrc0 =
        (larr == 0 ? Kh2 : larr == 1 ? Kl2 : larr == 2 ? Vh2 : Vl2) + headK + (size_t)lrow * 64;
    uint32_t lsw[8];
    #pragma unroll
    for (int seg = 0; seg < 8; seg++)
        lsw[seg] = (uint32_t)larr * 8192u + SW128((uint32_t)(lrow * 128 + seg * 16));

    #pragma unroll
    for (int seg = 0; seg < 8; seg++)
        CP16(STG(0) + lsw[seg], lsrc0 + seg * 8);
    CP_COMMIT();

    float oacc[8][4];
    #pragma unroll
    for (int nt = 0; nt < 8; nt++)
        #pragma unroll
        for (int r = 0; r < 4; r++) oacc[nt][r] = 0.f;
    float mrow[2] = {-1e30f, -1e30f}, lrowsum[2] = {0.f, 0.f};

    const float c2 = SCALE_ * 1.44269504088896340736f;
    const int wm = wid * 16;
    const uint32_t aOff = (uint32_t)((wm + (lane & 15)) * 128 + ((lane >> 4) << 4));
    const uint32_t kOff = (uint32_t)((lane & 15) * 128 + ((lane >> 4) << 4));
    const uint32_t vOff = (uint32_t)((lane & 15) * 128 + ((lane >> 4) << 4));

    const int iters = SK_ / 64;
    for (int i = 0; i < iters; i++) {
        __syncthreads();
        if (i + 1 < iters) {
            const __nv_bfloat16* src = lsrc0 + (size_t)(i + 1) * 64 * 64;
            const uint32_t stg = STG((i + 1) & 1);
            #pragma unroll
            for (int seg = 0; seg < 8; seg++)
                CP16(stg + lsw[seg], src + seg * 8);
        }
        CP_COMMIT();
        CP_WAIT1();
        __syncthreads();

        const uint32_t KH = STG(i & 1), KL = KH + 8192, VH = KH + 16384, VL = KH + 24576;

        float sacc[8][4];
        #pragma unroll
        for (int nt = 0; nt < 8; nt++)
            #pragma unroll
            for (int r = 0; r < 4; r++) sacc[nt][r] = 0.f;

        #pragma unroll
        for (int kc = 0; kc < 4; kc++) {
            uint32_t afh[4], afl[4];
            LDSM_X4(afh, QH + SW128(aOff + kc * 32));
            LDSM_X4(afl, QL + SW128(aOff + kc * 32));
            #pragma unroll
            for (int ntp = 0; ntp < 4; ntp++) {
                uint32_t b4h[4], b4l[4];
                uint32_t off = kOff + (uint32_t)(ntp * 2048 + kc * 32);
                LDSM_X4(b4h, KH + SW128(off));
                LDSM_X4(b4l, KL + SW128(off));
                uint32_t bh0[2] = {b4h[0], b4h[2]}, bh1[2] = {b4h[1], b4h[3]};
                uint32_t bl0[2] = {b4l[0], b4l[2]}, bl1[2] = {b4l[1], b4l[3]};
                MMA16816(sacc[2 * ntp],     afh, bh0);
                MMA16816(sacc[2 * ntp],     afh, bl0);
                MMA16816(sacc[2 * ntp],     afl, bh0);
                MMA16816(sacc[2 * ntp + 1], afh, bh1);
                MMA16816(sacc[2 * ntp + 1], afh, bl1);
                MMA16816(sacc[2 * ntp + 1], afl, bh1);
            }
        }

        float fac[2];
        #pragma unroll
        for (int j = 0; j < 2; j++) {
            float tmax = -1e30f;
            #pragma unroll
            for (int nt = 0; nt < 8; nt++)
                tmax = fmaxf(tmax, fmaxf(sacc[nt][2 * j], sacc[nt][2 * j + 1]));
            tmax = fmaxf(tmax, __shfl_xor_sync(0xffffffffu, tmax, 1));
            tmax = fmaxf(tmax, __shfl_xor_sync(0xffffffffu, tmax, 2));
            float mn = fmaxf(mrow[j], tmax);
            fac[j] = exp2f((mrow[j] - mn) * c2);
            mrow[j] = mn;
            float tsum = 0.f;
            #pragma unroll
            for (int nt = 0; nt < 8; nt++) {
                float p0 = exp2f((sacc[nt][2 * j]     - mn) * c2);
                float p1 = exp2f((sacc[nt][2 * j + 1] - mn) * c2);
                sacc[nt][2 * j] = p0; sacc[nt][2 * j + 1] = p1;
                tsum += p0 + p1;
            }
            tsum += __shfl_xor_sync(0xffffffffu, tsum, 1);
            tsum += __shfl_xor_sync(0xffffffffu, tsum, 2);
            lrowsum[j] = lrowsum[j] * fac[j] + tsum;
            #pragma unroll
            for (int nt = 0; nt < 8; nt++) {
                oacc[nt][2 * j]     *= fac[j];
                oacc[nt][2 * j + 1] *= fac[j];
            }
        }

        #pragma unroll
        for (int kc = 0; kc < 4; kc++) {
            uint32_t ah[4], al[4];
            split2(sacc[2 * kc][0],     sacc[2 * kc][1],     ah[0], al[0]);
            split2(sacc[2 * kc][2],     sacc[2 * kc][3],     ah[1], al[1]);
            split2(sacc[2 * kc + 1][0], sacc[2 * kc + 1][1], ah[2], al[2]);
            split2(sacc[2 * kc + 1][2], sacc[2 * kc + 1][3], ah[3], al[3]);
            #pragma unroll
            for (int ntp = 0; ntp < 4; ntp++) {
                uint32_t v4h[4], v4l[4];
                uint32_t off = vOff + (uint32_t)(kc * 2048 + ntp * 32);
                LDSM_X4_T(v4h, VH + SW128(off));
                LDSM_X4_T(v4l, VL + SW128(off));
                uint32_t bh0[2] = {v4h[0], v4h[1]}, bh1[2] = {v4h[2], v4h[3]};
                uint32_t bl0[2] = {v4l[0], v4l[1]}, bl1[2] = {v4l[2], v4l[3]};
                MMA16816(oacc[2 * ntp],     ah, bh0);
                MMA16816(oacc[2 * ntp],     ah, bl0);
                MMA16816(oacc[2 * ntp],     al, bh0);
                MMA16816(oacc[2 * ntp + 1], ah, bh1);
                MMA16816(oacc[2 * ntp + 1], ah, bl1);
                MMA16816(oacc[2 * ntp + 1], al, bh1);
            }
        }
    }

    // normalize + split-store ctx (hi/lo bf16) in [b, sq, D] layout
    const float inv0 = 1.f / lrowsum[0], inv1 = 1.f / lrowsum[1];
    const int r0 = q0 + wm + (lane >> 2);
    const int col0 = h * 64 + (lane & 3) * 2;
    #pragma unroll
    for (int nt = 0; nt < 8; nt++) {
        int col = col0 + nt * 8;
        size_t i0 = ((size_t)(b * SQ_ + r0))     * D_ + col;
        size_t i1 = ((size_t)(b * SQ_ + r0 + 8)) * D_ + col;
        uint32_t hi, lo;
        split2(oacc[nt][0] * inv0, oacc[nt][1] * inv0, hi, lo);
        *(uint32_t*)&ch[i0] = hi;  *(uint32_t*)&cl[i0] = lo;
        split2(oacc[nt][2] * inv1, oacc[nt][3] * inv1, hi, lo);
        *(uint32_t*)&ch[i1] = hi;  *(uint32_t*)&cl[i1] = lo;
    }
}

// ---------------------------------------------------------------------------
extern "C" void kernel_launch(void* const* d_in, const int* in_sizes, int n_in,
                              void* d_out, int out_size)
{
    const float* query     = (const float*)d_in[0];
    const float* key_value = (const float*)d_in[1];
    const float* Wq        = (const float*)d_in[2];
    const float* bq        = (const float*)d_in[3];
    const float* Wkv       = (const float*)d_in[4];
    const float* bkv       = (const float*)d_in[5];
    const float* Wo        = (const float*)d_in[6];
    const float* bo        = (const float*)d_in[7];
    float* out = (float*)d_out;

    __nv_bfloat16 *qh, *ql, *kh, *kl, *ch, *cl;
    __nv_bfloat16 *WqTh, *WqTl, *WkvTh, *WkvTl, *WoTh, *WoTl;
    __nv_bfloat16 *Qh2, *Ql2, *Kh2, *Kl2, *Vh2, *Vl2;
    cudaGetSymbolAddress((void**)&qh,   g_qh);   cudaGetSymbolAddress((void**)&ql, g_ql);
    cudaGetSymbolAddress((void**)&kh,   g_kh);   cudaGetSymbolAddress((void**)&kl, g_kl);
    cudaGetSymbolAddress((void**)&ch,   g_ch);   cudaGetSymbolAddress((void**)&cl, g_cl);
    cudaGetSymbolAddress((void**)&WqTh, g_WqTh); cudaGetSymbolAddress((void**)&WqTl, g_WqTl);
    cudaGetSymbolAddress((void**)&WkvTh,g_WkvTh);cudaGetSymbolAddress((void**)&WkvTl,g_WkvTl);
    cudaGetSymbolAddress((void**)&WoTh, g_WoTh); cudaGetSymbolAddress((void**)&WoTl, g_WoTl);
    cudaGetSymbolAddress((void**)&Qh2,  g_Qh2);  cudaGetSymbolAddress((void**)&Ql2, g_Ql2);
    cudaGetSymbolAddress((void**)&Kh2,  g_Kh2);  cudaGetSymbolAddress((void**)&Kl2, g_Kl2);
    cudaGetSymbolAddress((void**)&Vh2,  g_Vh2);  cudaGetSymbolAddress((void**)&Vl2, g_Vl2);

    cudaFuncSetAttribute(gemm_mma, cudaFuncAttributeMaxDynamicSharedMemorySize, GEMM_SMEM);
    cudaFuncSetAttribute(attn_tc,  cudaFuncAttributeMaxDynamicSharedMemorySize, ATTN_SMEM);

    // Weight transpose + split
    prep_wT<<<dim3(D_ / 32,     D_ / 32), dim3(32, 8)>>>(Wq,  WqTh,  WqTl,  D_, D_);
    prep_wT<<<dim3(2 * D_ / 32, D_ / 32), dim3(32, 8)>>>(Wkv, WkvTh, WkvTl, D_, 2 * D_);
    prep_wT<<<dim3(D_ / 32,     D_ / 32), dim3(32, 8)>>>(Wo,  WoTh,  WoTl,  D_, D_);

    // Activation splits
    prep_act<<<2048, 256>>>(query,     qh, ql, M_TOT * D_ / 4);
    prep_act<<<2048, 256>>>(key_value, kh, kl, M_TOT * D_ / 4);

    // Q projection -> per-head split (mode 1)
    gemm_mma<<<dim3(D_ / 128, M_TOT / 128), 256, GEMM_SMEM>>>(
        qh, ql, WqTh, WqTl, bq, nullptr, Qh2, Ql2, nullptr, nullptr, 1, D_, D_);
    // KV projection -> per-head split K + V (mode 2)
    gemm_mma<<<dim3(2 * D_ / 128, M_TOT / 128), 256, GEMM_SMEM>>>(
        kh, kl, WkvTh, WkvTl, bkv, nullptr, Kh2, Kl2, Vh2, Vl2, 2, 2 * D_, D_);

    // Attention -> split ctx (ch/cl)
    attn_tc<<<dim3(SQ_ / 128, H_, B_), 256, ATTN_SMEM>>>(
        Qh2, Ql2, Kh2, Kl2, Vh2, Vl2, ch, cl);

    // O projection -> fp32 out (mode 0)
    gemm_mma<<<dim3(D_ / 128, M_TOT / 128), 256, GEMM_SMEM>>>(
        ch, cl, WoTh, WoTl, bo, out, nullptr, nullptr, nullptr, nullptr, 0, D_, D_);
}